// round 1
// baseline (speedup 1.0000x reference)
#include <cuda_runtime.h>
#include <cstdint>

// ---------------- problem constants ----------------
#define T_TOK   8192
#define H_DIM   1024
#define I_DIM   512          // intermediate
#define E_EXP   8            // routed experts
#define EZ_EXP  12           // routed + zero experts
#define TOPK    2
#define SCALE_F 2.5f

typedef unsigned long long ull;

// ---------------- scratch (static device globals; no allocation) ----------------
__device__ int   g_top_idx[T_TOK * 2];
__device__ float g_top_w[T_TOK * 2];
__device__ float g_zero_scale[T_TOK];
__device__ int   g_counts[E_EXP];
__device__ int   g_rows[E_EXP * T_TOK];                 // slot ids (= token*2 + slot)
__device__ float g_act[(size_t)T_TOK * 2 * I_DIM];      // 32 MB
__device__ float g_y[(size_t)T_TOK * 2 * H_DIM];        // 64 MB

// ---------------- f32x2 helpers ----------------
__device__ __forceinline__ ull pack2(float lo, float hi) {
    ull r; asm("mov.b64 %0, {%1,%2};" : "=l"(r) : "f"(lo), "f"(hi)); return r;
}
__device__ __forceinline__ void unpack2(ull v, float& lo, float& hi) {
    asm("mov.b64 {%0,%1}, %2;" : "=f"(lo), "=f"(hi) : "l"(v));
}
__device__ __forceinline__ ull fma2(ull a, ull b, ull c) {
    ull d; asm("fma.rn.f32x2 %0, %1, %2, %3;" : "=l"(d) : "l"(a), "l"(b), "l"(c)); return d;
}

// ============================================================================
// Kernel 1: router. 8 tokens per block (one per warp). router_w staged in smem.
// ============================================================================
__global__ void __launch_bounds__(256) router_kernel(
    const float* __restrict__ x,
    const float* __restrict__ rw,
    const float* __restrict__ bias)
{
    __shared__ float srw[EZ_EXP * H_DIM];   // 48 KB exactly
    const int tid = threadIdx.x;
    for (int i = tid; i < EZ_EXP * H_DIM; i += 256) srw[i] = rw[i];
    __syncthreads();

    const int warp = tid >> 5, lane = tid & 31;
    const int t = blockIdx.x * 8 + warp;
    const float* xr = x + (size_t)t * H_DIM;

    float xv[32];
#pragma unroll
    for (int j = 0; j < 32; j++) xv[j] = xr[lane + 32 * j];

    float logits[EZ_EXP];
#pragma unroll
    for (int e = 0; e < EZ_EXP; e++) {
        const float* wr = srw + e * H_DIM;
        float acc = 0.f;
#pragma unroll
        for (int j = 0; j < 32; j++) acc += xv[j] * wr[lane + 32 * j];
#pragma unroll
        for (int off = 16; off; off >>= 1) acc += __shfl_xor_sync(0xffffffffu, acc, off);
        logits[e] = acc;   // all lanes hold full sum
    }

    if (lane == 0) {
        float mx = logits[0];
#pragma unroll
        for (int e = 1; e < EZ_EXP; e++) mx = fmaxf(mx, logits[e]);
        float sc[EZ_EXP], s = 0.f;
#pragma unroll
        for (int e = 0; e < EZ_EXP; e++) { sc[e] = __expf(logits[e] - mx); s += sc[e]; }
        const float inv = 1.f / s;
        float bsc[EZ_EXP];
#pragma unroll
        for (int e = 0; e < EZ_EXP; e++) { sc[e] *= inv; bsc[e] = sc[e] + bias[e]; }

        // top-2 of biased scores, ties -> lower index (matches lax.top_k)
        int i1 = 0;
#pragma unroll
        for (int e = 1; e < EZ_EXP; e++) if (bsc[e] > bsc[i1]) i1 = e;
        int i2 = (i1 == 0) ? 1 : 0;
#pragma unroll
        for (int e = 0; e < EZ_EXP; e++) if (e != i1 && bsc[e] > bsc[i2]) i2 = e;

        const float w1 = sc[i1], w2v = sc[i2];
        g_top_idx[2 * t]     = i1;
        g_top_idx[2 * t + 1] = i2;
        g_top_w[2 * t]       = w1;
        g_top_w[2 * t + 1]   = w2v;
        float zs = 0.f;
        if (i1 >= E_EXP) zs += w1;
        if (i2 >= E_EXP) zs += w2v;
        g_zero_scale[t] = zs;
    }
}

// ============================================================================
// Kernel 2: stable per-expert compaction (one block per expert, deterministic).
// ============================================================================
__global__ void __launch_bounds__(256) build_lists_kernel()
{
    const int e = blockIdx.x;
    const int tid = threadIdx.x;
    const int lane = tid & 31, w = tid >> 5;
    __shared__ int warp_tot[8];
    __shared__ int s_base;
    if (tid == 0) s_base = 0;
    __syncthreads();

    for (int base = 0; base < 2 * T_TOK; base += 256) {
        const int slot = base + tid;
        const int flag = (g_top_idx[slot] == e) ? 1 : 0;
        const unsigned bal = __ballot_sync(0xffffffffu, flag);
        const int pre = __popc(bal & ((1u << lane) - 1u));
        if (lane == 0) warp_tot[w] = __popc(bal);
        __syncthreads();
        int woff = 0;
        for (int i = 0; i < w; i++) woff += warp_tot[i];
        if (flag) g_rows[e * T_TOK + s_base + woff + pre] = slot;
        __syncthreads();
        if (tid == 0) {
            int tt = 0;
            for (int i = 0; i < 8; i++) tt += warp_tot[i];
            s_base += tt;
        }
        __syncthreads();
    }
    if (tid == 0) g_counts[e] = s_base;
}

// ============================================================================
// Kernel 3: up-projection GEMM + SiLU*up epilogue.
// Block tile: 64 gathered rows x 32 act columns (needs 64 w13 rows: 32 gate + 32 up).
// 256 threads, each owns 4(m) x 4(n) outputs held as f32x2 pairs.
// grid: (E*128, I/32)
// ============================================================================
__global__ void __launch_bounds__(256) up_gemm_kernel(
    const float* __restrict__ x,
    const float* __restrict__ w13)
{
    const int e  = blockIdx.x >> 7;
    const int mt = blockIdx.x & 127;
    const int cnt = g_counts[e];
    const int m0 = mt * 64;
    if (m0 >= cnt) return;
    const int rcount = min(64, cnt - m0);

    __shared__ int srows[64];
    __shared__ __align__(16) float As[2][16][64];
    __shared__ __align__(16) float Bs[2][16][64];

    const int tid = threadIdx.x;
    if (tid < 64) srows[tid] = g_rows[e * T_TOK + m0 + min(tid, rcount - 1)];
    __syncthreads();

    const int lrow = tid >> 2;          // 0..63
    const int lk4  = (tid & 3) * 4;     // 0,4,8,12
    const int nBase = blockIdx.y * 32;

    const int tokA = srows[lrow] >> 1;
    const float* aptr = x + (size_t)tokA * H_DIM + lk4;
    const int grow = (lrow < 32) ? (nBase + lrow) : (I_DIM + nBase + (lrow - 32));
    const float* bptr = w13 + ((size_t)e * (2 * I_DIM) + grow) * H_DIM + lk4;

    const int tx = tid & 15;
    const int ty = tid >> 4;

    ull C[4][2];
#pragma unroll
    for (int i = 0; i < 4; i++) { C[i][0] = pack2(0.f, 0.f); C[i][1] = pack2(0.f, 0.f); }

    float4 av = *(const float4*)(aptr);
    float4 bv = *(const float4*)(bptr);

    int buf = 0;
#pragma unroll 1
    for (int kt = 0; kt < 64; kt++) {
        As[buf][lk4 + 0][lrow] = av.x; As[buf][lk4 + 1][lrow] = av.y;
        As[buf][lk4 + 2][lrow] = av.z; As[buf][lk4 + 3][lrow] = av.w;
        Bs[buf][lk4 + 0][lrow] = bv.x; Bs[buf][lk4 + 1][lrow] = bv.y;
        Bs[buf][lk4 + 2][lrow] = bv.z; Bs[buf][lk4 + 3][lrow] = bv.w;
        __syncthreads();
        if (kt < 63) {
            av = *(const float4*)(aptr + (kt + 1) * 16);
            bv = *(const float4*)(bptr + (kt + 1) * 16);
        }
#pragma unroll
        for (int kk = 0; kk < 16; kk++) {
            const ull b0 = *(const ull*)&Bs[buf][kk][2 * tx];
            const ull b1 = *(const ull*)&Bs[buf][kk][2 * tx + 32];
#pragma unroll
            for (int i = 0; i < 4; i++) {
                const float a = As[buf][kk][4 * ty + i];
                const ull ap = pack2(a, a);
                C[i][0] = fma2(ap, b0, C[i][0]);
                C[i][1] = fma2(ap, b1, C[i][1]);
            }
        }
        buf ^= 1;
    }

#pragma unroll
    for (int i = 0; i < 4; i++) {
        const int m = 4 * ty + i;
        if (m < rcount) {
            const int slot = srows[m];
            float g0, g1, u0, u1;
            unpack2(C[i][0], g0, g1);   // gate cols 2tx, 2tx+1
            unpack2(C[i][1], u0, u1);   // up   cols 2tx, 2tx+1
            const float a0 = g0 * (1.f / (1.f + __expf(-g0))) * u0;
            const float a1 = g1 * (1.f / (1.f + __expf(-g1))) * u1;
            float2 v; v.x = a0; v.y = a1;
            *(float2*)(g_act + (size_t)slot * I_DIM + nBase + 2 * tx) = v;
        }
    }
}

// ============================================================================
// Kernel 4: down-projection GEMM; epilogue multiplies gate weight * SCALE.
// Block tile: 64 rows x 64 H-columns, K=512. grid: (E*128, H/64)
// ============================================================================
__global__ void __launch_bounds__(256) down_gemm_kernel(
    const float* __restrict__ w2)
{
    const int e  = blockIdx.x >> 7;
    const int mt = blockIdx.x & 127;
    const int cnt = g_counts[e];
    const int m0 = mt * 64;
    if (m0 >= cnt) return;
    const int rcount = min(64, cnt - m0);

    __shared__ int srows[64];
    __shared__ __align__(16) float As[2][16][64];
    __shared__ __align__(16) float Bs[2][16][64];

    const int tid = threadIdx.x;
    if (tid < 64) srows[tid] = g_rows[e * T_TOK + m0 + min(tid, rcount - 1)];
    __syncthreads();

    const int lrow = tid >> 2;
    const int lk4  = (tid & 3) * 4;
    const int hBase = blockIdx.y * 64;

    const float* aptr = g_act + (size_t)srows[lrow] * I_DIM + lk4;
    const float* bptr = w2 + ((size_t)e * H_DIM + hBase + lrow) * I_DIM + lk4;

    const int tx = tid & 15;
    const int ty = tid >> 4;

    ull C[4][2];
#pragma unroll
    for (int i = 0; i < 4; i++) { C[i][0] = pack2(0.f, 0.f); C[i][1] = pack2(0.f, 0.f); }

    float4 av = *(const float4*)(aptr);
    float4 bv = *(const float4*)(bptr);

    int buf = 0;
#pragma unroll 1
    for (int kt = 0; kt < 32; kt++) {
        As[buf][lk4 + 0][lrow] = av.x; As[buf][lk4 + 1][lrow] = av.y;
        As[buf][lk4 + 2][lrow] = av.z; As[buf][lk4 + 3][lrow] = av.w;
        Bs[buf][lk4 + 0][lrow] = bv.x; Bs[buf][lk4 + 1][lrow] = bv.y;
        Bs[buf][lk4 + 2][lrow] = bv.z; Bs[buf][lk4 + 3][lrow] = bv.w;
        __syncthreads();
        if (kt < 31) {
            av = *(const float4*)(aptr + (kt + 1) * 16);
            bv = *(const float4*)(bptr + (kt + 1) * 16);
        }
#pragma unroll
        for (int kk = 0; kk < 16; kk++) {
            const ull b0 = *(const ull*)&Bs[buf][kk][2 * tx];
            const ull b1 = *(const ull*)&Bs[buf][kk][2 * tx + 32];
#pragma unroll
            for (int i = 0; i < 4; i++) {
                const float a = As[buf][kk][4 * ty + i];
                const ull ap = pack2(a, a);
                C[i][0] = fma2(ap, b0, C[i][0]);
                C[i][1] = fma2(ap, b1, C[i][1]);
            }
        }
        buf ^= 1;
    }

#pragma unroll
    for (int i = 0; i < 4; i++) {
        const int m = 4 * ty + i;
        if (m < rcount) {
            const int slot = srows[m];
            const float w = g_top_w[slot] * SCALE_F;
            float c0, c1, c2, c3;
            unpack2(C[i][0], c0, c1);   // cols hBase+2tx, +1
            unpack2(C[i][1], c2, c3);   // cols hBase+2tx+32, +33
            float* dst = g_y + (size_t)slot * H_DIM + hBase + 2 * tx;
            float2 v0; v0.x = w * c0; v0.y = w * c1;
            float2 v1; v1.x = w * c2; v1.y = w * c3;
            *(float2*)(dst)      = v0;
            *(float2*)(dst + 32) = v1;
        }
    }
}

// ============================================================================
// Kernel 5: finalize. out = routed-slot sums + zero_scale * x. One block/token.
// ============================================================================
__global__ void __launch_bounds__(256) finalize_kernel(
    const float* __restrict__ x,
    float* __restrict__ out)
{
    const int t = blockIdx.x;
    const float zs = g_zero_scale[t];
    const bool r0 = g_top_idx[2 * t]     < E_EXP;
    const bool r1 = g_top_idx[2 * t + 1] < E_EXP;
    const int h = threadIdx.x * 4;

    float4 xv = *(const float4*)(x + (size_t)t * H_DIM + h);
    float4 o;
    o.x = zs * xv.x; o.y = zs * xv.y; o.z = zs * xv.z; o.w = zs * xv.w;
    if (r0) {
        float4 y = *(const float4*)(g_y + (size_t)(2 * t) * H_DIM + h);
        o.x += y.x; o.y += y.y; o.z += y.z; o.w += y.w;
    }
    if (r1) {
        float4 y = *(const float4*)(g_y + (size_t)(2 * t + 1) * H_DIM + h);
        o.x += y.x; o.y += y.y; o.z += y.z; o.w += y.w;
    }
    *(float4*)(out + (size_t)t * H_DIM + h) = o;
}

// ============================================================================
// launch
// ============================================================================
extern "C" void kernel_launch(void* const* d_in, const int* in_sizes, int n_in,
                              void* d_out, int out_size)
{
    const float* x    = (const float*)d_in[0];   // [T, H]
    const float* rw   = (const float*)d_in[1];   // [12, H]
    const float* bias = (const float*)d_in[2];   // [12]
    const float* w13  = (const float*)d_in[3];   // [E, 2I, H]
    const float* w2   = (const float*)d_in[4];   // [E, H, I]
    float* out = (float*)d_out;

    router_kernel<<<T_TOK / 8, 256>>>(x, rw, bias);
    build_lists_kernel<<<E_EXP, 256>>>();

    dim3 g3(E_EXP * 128, I_DIM / 32);   // 1024 x 16
    up_gemm_kernel<<<g3, 256>>>(x, w13);

    dim3 g4(E_EXP * 128, H_DIM / 64);   // 1024 x 16
    down_gemm_kernel<<<g4, 256>>>(w2);

    finalize_kernel<<<T_TOK, 256>>>(x, out);
}

// round 2
// speedup vs baseline: 1.0010x; 1.0010x over previous
#include <cuda_runtime.h>
#include <cstdint>

// ---------------- problem constants ----------------
#define T_TOK   8192
#define H_DIM   1024
#define I_DIM   512          // intermediate
#define E_EXP   8            // routed experts
#define EZ_EXP  12           // routed + zero experts
#define TOPK    2
#define SCALE_F 2.5f

typedef unsigned long long ull;

// ---------------- scratch (static device globals; no allocation) ----------------
__device__ int   g_top_idx[T_TOK * 2];
__device__ float g_top_w[T_TOK * 2];
__device__ float g_zero_scale[T_TOK];
__device__ int   g_counts[E_EXP];
__device__ int   g_rows[E_EXP * T_TOK];                 // slot ids (= token*2 + slot)
__device__ float g_act[(size_t)T_TOK * 2 * I_DIM];      // 32 MB
__device__ float g_y[(size_t)T_TOK * 2 * H_DIM];        // 64 MB

// ---------------- f32x2 helpers ----------------
__device__ __forceinline__ ull pack2(float lo, float hi) {
    ull r; asm("mov.b64 %0, {%1,%2};" : "=l"(r) : "f"(lo), "f"(hi)); return r;
}
__device__ __forceinline__ void unpack2(ull v, float& lo, float& hi) {
    asm("mov.b64 {%0,%1}, %2;" : "=f"(lo), "=f"(hi) : "l"(v));
}
__device__ __forceinline__ ull fma2(ull a, ull b, ull c) {
    ull d; asm("fma.rn.f32x2 %0, %1, %2, %3;" : "=l"(d) : "l"(a), "l"(b), "l"(c)); return d;
}

// ============================================================================
// Kernel 1: router. 8 tokens per block (one per warp). router_w staged in smem.
// ============================================================================
__global__ void __launch_bounds__(256) router_kernel(
    const float* __restrict__ x,
    const float* __restrict__ rw,
    const float* __restrict__ bias)
{
    __shared__ float srw[EZ_EXP * H_DIM];   // 48 KB exactly
    const int tid = threadIdx.x;
    for (int i = tid; i < EZ_EXP * H_DIM; i += 256) srw[i] = rw[i];
    __syncthreads();

    const int warp = tid >> 5, lane = tid & 31;
    const int t = blockIdx.x * 8 + warp;
    const float* xr = x + (size_t)t * H_DIM;

    float xv[32];
#pragma unroll
    for (int j = 0; j < 32; j++) xv[j] = xr[lane + 32 * j];

    float logits[EZ_EXP];
#pragma unroll
    for (int e = 0; e < EZ_EXP; e++) {
        const float* wr = srw + e * H_DIM;
        float acc = 0.f;
#pragma unroll
        for (int j = 0; j < 32; j++) acc += xv[j] * wr[lane + 32 * j];
#pragma unroll
        for (int off = 16; off; off >>= 1) acc += __shfl_xor_sync(0xffffffffu, acc, off);
        logits[e] = acc;   // all lanes hold full sum
    }

    if (lane == 0) {
        float mx = logits[0];
#pragma unroll
        for (int e = 1; e < EZ_EXP; e++) mx = fmaxf(mx, logits[e]);
        float sc[EZ_EXP], s = 0.f;
#pragma unroll
        for (int e = 0; e < EZ_EXP; e++) { sc[e] = __expf(logits[e] - mx); s += sc[e]; }
        const float inv = 1.f / s;
        float bsc[EZ_EXP];
#pragma unroll
        for (int e = 0; e < EZ_EXP; e++) { sc[e] *= inv; bsc[e] = sc[e] + bias[e]; }

        // top-2 of biased scores, ties -> lower index (matches lax.top_k)
        int i1 = 0;
#pragma unroll
        for (int e = 1; e < EZ_EXP; e++) if (bsc[e] > bsc[i1]) i1 = e;
        int i2 = (i1 == 0) ? 1 : 0;
#pragma unroll
        for (int e = 0; e < EZ_EXP; e++) if (e != i1 && bsc[e] > bsc[i2]) i2 = e;

        const float w1 = sc[i1], w2v = sc[i2];
        g_top_idx[2 * t]     = i1;
        g_top_idx[2 * t + 1] = i2;
        g_top_w[2 * t]       = w1;
        g_top_w[2 * t + 1]   = w2v;
        float zs = 0.f;
        if (i1 >= E_EXP) zs += w1;
        if (i2 >= E_EXP) zs += w2v;
        g_zero_scale[t] = zs;
    }
}

// ============================================================================
// Kernel 2: stable per-expert compaction (one block per expert, deterministic).
// ============================================================================
__global__ void __launch_bounds__(256) build_lists_kernel()
{
    const int e = blockIdx.x;
    const int tid = threadIdx.x;
    const int lane = tid & 31, w = tid >> 5;
    __shared__ int warp_tot[8];
    __shared__ int s_base;
    if (tid == 0) s_base = 0;
    __syncthreads();

    for (int base = 0; base < 2 * T_TOK; base += 256) {
        const int slot = base + tid;
        const int flag = (g_top_idx[slot] == e) ? 1 : 0;
        const unsigned bal = __ballot_sync(0xffffffffu, flag);
        const int pre = __popc(bal & ((1u << lane) - 1u));
        if (lane == 0) warp_tot[w] = __popc(bal);
        __syncthreads();
        int woff = 0;
        for (int i = 0; i < w; i++) woff += warp_tot[i];
        if (flag) g_rows[e * T_TOK + s_base + woff + pre] = slot;
        __syncthreads();
        if (tid == 0) {
            int tt = 0;
            for (int i = 0; i < 8; i++) tt += warp_tot[i];
            s_base += tt;
        }
        __syncthreads();
    }
    if (tid == 0) g_counts[e] = s_base;
}

// ============================================================================
// Kernel 3: up-projection GEMM + SiLU*up epilogue.
// Block tile: 64 gathered rows x 32 act columns (needs 64 w13 rows: 32 gate + 32 up).
// 256 threads, each owns 4(m) x 4(n) outputs held as f32x2 pairs.
// grid: (E*128, I/32)
// ============================================================================
__global__ void __launch_bounds__(256) up_gemm_kernel(
    const float* __restrict__ x,
    const float* __restrict__ w13)
{
    const int e  = blockIdx.x >> 7;
    const int mt = blockIdx.x & 127;
    const int cnt = g_counts[e];
    const int m0 = mt * 64;
    if (m0 >= cnt) return;
    const int rcount = min(64, cnt - m0);

    __shared__ int srows[64];
    __shared__ __align__(16) float As[2][16][64];
    __shared__ __align__(16) float Bs[2][16][64];

    const int tid = threadIdx.x;
    if (tid < 64) srows[tid] = g_rows[e * T_TOK + m0 + min(tid, rcount - 1)];
    __syncthreads();

    const int lrow = tid >> 2;          // 0..63
    const int lk4  = (tid & 3) * 4;     // 0,4,8,12
    const int nBase = blockIdx.y * 32;

    const int tokA = srows[lrow] >> 1;
    const float* aptr = x + (size_t)tokA * H_DIM + lk4;
    const int grow = (lrow < 32) ? (nBase + lrow) : (I_DIM + nBase + (lrow - 32));
    const float* bptr = w13 + ((size_t)e * (2 * I_DIM) + grow) * H_DIM + lk4;

    const int tx = tid & 15;
    const int ty = tid >> 4;

    ull C[4][2];
#pragma unroll
    for (int i = 0; i < 4; i++) { C[i][0] = pack2(0.f, 0.f); C[i][1] = pack2(0.f, 0.f); }

    float4 av = *(const float4*)(aptr);
    float4 bv = *(const float4*)(bptr);

    int buf = 0;
#pragma unroll 1
    for (int kt = 0; kt < 64; kt++) {
        As[buf][lk4 + 0][lrow] = av.x; As[buf][lk4 + 1][lrow] = av.y;
        As[buf][lk4 + 2][lrow] = av.z; As[buf][lk4 + 3][lrow] = av.w;
        Bs[buf][lk4 + 0][lrow] = bv.x; Bs[buf][lk4 + 1][lrow] = bv.y;
        Bs[buf][lk4 + 2][lrow] = bv.z; Bs[buf][lk4 + 3][lrow] = bv.w;
        __syncthreads();
        if (kt < 63) {
            av = *(const float4*)(aptr + (kt + 1) * 16);
            bv = *(const float4*)(bptr + (kt + 1) * 16);
        }
#pragma unroll
        for (int kk = 0; kk < 16; kk++) {
            const ull b0 = *(const ull*)&Bs[buf][kk][2 * tx];
            const ull b1 = *(const ull*)&Bs[buf][kk][2 * tx + 32];
#pragma unroll
            for (int i = 0; i < 4; i++) {
                const float a = As[buf][kk][4 * ty + i];
                const ull ap = pack2(a, a);
                C[i][0] = fma2(ap, b0, C[i][0]);
                C[i][1] = fma2(ap, b1, C[i][1]);
            }
        }
        buf ^= 1;
    }

#pragma unroll
    for (int i = 0; i < 4; i++) {
        const int m = 4 * ty + i;
        if (m < rcount) {
            const int slot = srows[m];
            float g0, g1, u0, u1;
            unpack2(C[i][0], g0, g1);   // gate cols 2tx, 2tx+1
            unpack2(C[i][1], u0, u1);   // up   cols 2tx, 2tx+1
            const float a0 = g0 * (1.f / (1.f + __expf(-g0))) * u0;
            const float a1 = g1 * (1.f / (1.f + __expf(-g1))) * u1;
            float2 v; v.x = a0; v.y = a1;
            *(float2*)(g_act + (size_t)slot * I_DIM + nBase + 2 * tx) = v;
        }
    }
}

// ============================================================================
// Kernel 4: down-projection GEMM; epilogue multiplies gate weight * SCALE.
// Block tile: 64 rows x 64 H-columns, K=512. grid: (E*128, H/64)
// ============================================================================
__global__ void __launch_bounds__(256) down_gemm_kernel(
    const float* __restrict__ w2)
{
    const int e  = blockIdx.x >> 7;
    const int mt = blockIdx.x & 127;
    const int cnt = g_counts[e];
    const int m0 = mt * 64;
    if (m0 >= cnt) return;
    const int rcount = min(64, cnt - m0);

    __shared__ int srows[64];
    __shared__ __align__(16) float As[2][16][64];
    __shared__ __align__(16) float Bs[2][16][64];

    const int tid = threadIdx.x;
    if (tid < 64) srows[tid] = g_rows[e * T_TOK + m0 + min(tid, rcount - 1)];
    __syncthreads();

    const int lrow = tid >> 2;
    const int lk4  = (tid & 3) * 4;
    const int hBase = blockIdx.y * 64;

    const float* aptr = g_act + (size_t)srows[lrow] * I_DIM + lk4;
    const float* bptr = w2 + ((size_t)e * H_DIM + hBase + lrow) * I_DIM + lk4;

    const int tx = tid & 15;
    const int ty = tid >> 4;

    ull C[4][2];
#pragma unroll
    for (int i = 0; i < 4; i++) { C[i][0] = pack2(0.f, 0.f); C[i][1] = pack2(0.f, 0.f); }

    float4 av = *(const float4*)(aptr);
    float4 bv = *(const float4*)(bptr);

    int buf = 0;
#pragma unroll 1
    for (int kt = 0; kt < 32; kt++) {
        As[buf][lk4 + 0][lrow] = av.x; As[buf][lk4 + 1][lrow] = av.y;
        As[buf][lk4 + 2][lrow] = av.z; As[buf][lk4 + 3][lrow] = av.w;
        Bs[buf][lk4 + 0][lrow] = bv.x; Bs[buf][lk4 + 1][lrow] = bv.y;
        Bs[buf][lk4 + 2][lrow] = bv.z; Bs[buf][lk4 + 3][lrow] = bv.w;
        __syncthreads();
        if (kt < 31) {
            av = *(const float4*)(aptr + (kt + 1) * 16);
            bv = *(const float4*)(bptr + (kt + 1) * 16);
        }
#pragma unroll
        for (int kk = 0; kk < 16; kk++) {
            const ull b0 = *(const ull*)&Bs[buf][kk][2 * tx];
            const ull b1 = *(const ull*)&Bs[buf][kk][2 * tx + 32];
#pragma unroll
            for (int i = 0; i < 4; i++) {
                const float a = As[buf][kk][4 * ty + i];
                const ull ap = pack2(a, a);
                C[i][0] = fma2(ap, b0, C[i][0]);
                C[i][1] = fma2(ap, b1, C[i][1]);
            }
        }
        buf ^= 1;
    }

#pragma unroll
    for (int i = 0; i < 4; i++) {
        const int m = 4 * ty + i;
        if (m < rcount) {
            const int slot = srows[m];
            const float w = g_top_w[slot] * SCALE_F;
            float c0, c1, c2, c3;
            unpack2(C[i][0], c0, c1);   // cols hBase+2tx, +1
            unpack2(C[i][1], c2, c3);   // cols hBase+2tx+32, +33
            float* dst = g_y + (size_t)slot * H_DIM + hBase + 2 * tx;
            float2 v0; v0.x = w * c0; v0.y = w * c1;
            float2 v1; v1.x = w * c2; v1.y = w * c3;
            *(float2*)(dst)      = v0;
            *(float2*)(dst + 32) = v1;
        }
    }
}

// ============================================================================
// Kernel 5: finalize. out = routed-slot sums + zero_scale * x. One block/token.
// ============================================================================
__global__ void __launch_bounds__(256) finalize_kernel(
    const float* __restrict__ x,
    float* __restrict__ out)
{
    const int t = blockIdx.x;
    const float zs = g_zero_scale[t];
    const bool r0 = g_top_idx[2 * t]     < E_EXP;
    const bool r1 = g_top_idx[2 * t + 1] < E_EXP;
    const int h = threadIdx.x * 4;

    float4 xv = *(const float4*)(x + (size_t)t * H_DIM + h);
    float4 o;
    o.x = zs * xv.x; o.y = zs * xv.y; o.z = zs * xv.z; o.w = zs * xv.w;
    if (r0) {
        float4 y = *(const float4*)(g_y + (size_t)(2 * t) * H_DIM + h);
        o.x += y.x; o.y += y.y; o.z += y.z; o.w += y.w;
    }
    if (r1) {
        float4 y = *(const float4*)(g_y + (size_t)(2 * t + 1) * H_DIM + h);
        o.x += y.x; o.y += y.y; o.z += y.z; o.w += y.w;
    }
    *(float4*)(out + (size_t)t * H_DIM + h) = o;
}

// ============================================================================
// launch
// ============================================================================
extern "C" void kernel_launch(void* const* d_in, const int* in_sizes, int n_in,
                              void* d_out, int out_size)
{
    const float* x    = (const float*)d_in[0];   // [T, H]
    const float* rw   = (const float*)d_in[1];   // [12, H]
    const float* bias = (const float*)d_in[2];   // [12]
    const float* w13  = (const float*)d_in[3];   // [E, 2I, H]
    const float* w2   = (const float*)d_in[4];   // [E, H, I]
    float* out = (float*)d_out;

    router_kernel<<<T_TOK / 8, 256>>>(x, rw, bias);
    build_lists_kernel<<<E_EXP, 256>>>();

    dim3 g3(E_EXP * 128, I_DIM / 32);   // 1024 x 16
    up_gemm_kernel<<<g3, 256>>>(x, w13);

    dim3 g4(E_EXP * 128, H_DIM / 64);   // 1024 x 16
    down_gemm_kernel<<<g4, 256>>>(w2);

    finalize_kernel<<<T_TOK, 256>>>(x, out);
}

// round 4
// speedup vs baseline: 2.3940x; 2.3916x over previous
#include <cuda_runtime.h>
#include <cuda_bf16.h>
#include <cstdint>

#define T_TOK   8192
#define H_DIM   1024
#define I_DIM   512
#define E_EXP   8
#define EZ_EXP  12
#define SCALE_F 2.5f

typedef unsigned int u32;
typedef unsigned long long u64;

// ---------------- scratch (device globals; no allocation) ----------------
__device__ int   g_top_idx[T_TOK * 2];
__device__ float g_top_w[T_TOK * 2];
__device__ float g_zero_scale[T_TOK];
__device__ int   g_counts[E_EXP];
__device__ int   g_rows[E_EXP * T_TOK];                 // slot ids (token*2+k)
__device__ float g_act[(size_t)T_TOK * 2 * I_DIM];      // 32 MB, indexed by slot
__device__ float g_y[(size_t)T_TOK * 2 * H_DIM];        // 64 MB, indexed by slot

// ---------------- helpers ----------------
__device__ __forceinline__ u32 smem_u32(const void* p) {
    u32 a;
    asm("{ .reg .u64 t; cvta.to.shared.u64 t, %1; cvt.u32.u64 %0, t; }" : "=r"(a) : "l"(p));
    return a;
}

#define STS128U(addr, v) \
    asm volatile("st.shared.v4.b32 [%0], {%1,%2,%3,%4};" \
                 :: "r"((u32)(addr)), "r"((v).x), "r"((v).y), "r"((v).z), "r"((v).w) : "memory")

__device__ __forceinline__ void ldsm4(u32& r0, u32& r1, u32& r2, u32& r3, u32 addr) {
    asm volatile("ldmatrix.sync.aligned.m8n8.x4.shared.b16 {%0,%1,%2,%3}, [%4];"
                 : "=r"(r0), "=r"(r1), "=r"(r2), "=r"(r3) : "r"(addr));
}

__device__ __forceinline__ void mma_bf16(float* d, const u32* a, u32 b0, u32 b1) {
    asm volatile("mma.sync.aligned.m16n8k16.row.col.f32.bf16.bf16.f32 "
        "{%0,%1,%2,%3}, {%4,%5,%6,%7}, {%8,%9}, {%0,%1,%2,%3};"
        : "+f"(d[0]), "+f"(d[1]), "+f"(d[2]), "+f"(d[3])
        : "r"(a[0]), "r"(a[1]), "r"(a[2]), "r"(a[3]), "r"(b0), "r"(b1));
}

// split 2 floats -> bf16x2 hi (mem order [v0,v1]) + bf16x2 lo residual
__device__ __forceinline__ u32 bfsplit(float v0, float v1, u32& lo) {
    u32 h; asm("cvt.rn.bf16x2.f32 %0, %1, %2;" : "=r"(h) : "f"(v1), "f"(v0));
    float h0 = __uint_as_float(h << 16);
    float h1 = __uint_as_float(h & 0xffff0000u);
    u32 l; asm("cvt.rn.bf16x2.f32 %0, %1, %2;" : "=r"(l) : "f"(v1 - h1), "f"(v0 - h0));
    lo = l; return h;
}
__device__ __forceinline__ void cvt8(const float4& a, const float4& b, uint4& hi, uint4& lo) {
    hi.x = bfsplit(a.x, a.y, lo.x);
    hi.y = bfsplit(a.z, a.w, lo.y);
    hi.z = bfsplit(b.x, b.y, lo.z);
    hi.w = bfsplit(b.z, b.w, lo.w);
}

// ============================================================================
// Kernel 1: router (proven)
// ============================================================================
__global__ void __launch_bounds__(256) router_kernel(
    const float* __restrict__ x, const float* __restrict__ rw, const float* __restrict__ bias)
{
    __shared__ float srw[EZ_EXP * H_DIM];
    const int tid = threadIdx.x;
    for (int i = tid; i < EZ_EXP * H_DIM; i += 256) srw[i] = rw[i];
    __syncthreads();

    const int warp = tid >> 5, lane = tid & 31;
    const int t = blockIdx.x * 8 + warp;
    const float* xr = x + (size_t)t * H_DIM;

    float xv[32];
#pragma unroll
    for (int j = 0; j < 32; j++) xv[j] = xr[lane + 32 * j];

    float logits[EZ_EXP];
#pragma unroll
    for (int e = 0; e < EZ_EXP; e++) {
        const float* wr = srw + e * H_DIM;
        float acc = 0.f;
#pragma unroll
        for (int j = 0; j < 32; j++) acc += xv[j] * wr[lane + 32 * j];
#pragma unroll
        for (int off = 16; off; off >>= 1) acc += __shfl_xor_sync(0xffffffffu, acc, off);
        logits[e] = acc;
    }

    if (lane == 0) {
        float mx = logits[0];
#pragma unroll
        for (int e = 1; e < EZ_EXP; e++) mx = fmaxf(mx, logits[e]);
        float sc[EZ_EXP], s = 0.f;
#pragma unroll
        for (int e = 0; e < EZ_EXP; e++) { sc[e] = __expf(logits[e] - mx); s += sc[e]; }
        const float inv = 1.f / s;
        float bsc[EZ_EXP];
#pragma unroll
        for (int e = 0; e < EZ_EXP; e++) { sc[e] *= inv; bsc[e] = sc[e] + bias[e]; }

        int i1 = 0;
#pragma unroll
        for (int e = 1; e < EZ_EXP; e++) if (bsc[e] > bsc[i1]) i1 = e;
        int i2 = (i1 == 0) ? 1 : 0;
#pragma unroll
        for (int e = 0; e < EZ_EXP; e++) if (e != i1 && bsc[e] > bsc[i2]) i2 = e;

        const float w1 = sc[i1], w2v = sc[i2];
        g_top_idx[2 * t] = i1;  g_top_idx[2 * t + 1] = i2;
        g_top_w[2 * t] = w1;    g_top_w[2 * t + 1] = w2v;
        float zs = 0.f;
        if (i1 >= E_EXP) zs += w1;
        if (i2 >= E_EXP) zs += w2v;
        g_zero_scale[t] = zs;
    }
}

// ============================================================================
// Kernel 2: stable per-expert compaction (proven, deterministic)
// ============================================================================
__global__ void __launch_bounds__(256) build_lists_kernel()
{
    const int e = blockIdx.x;
    const int tid = threadIdx.x;
    const int lane = tid & 31, w = tid >> 5;
    __shared__ int warp_tot[8];
    __shared__ int s_base;
    if (tid == 0) s_base = 0;
    __syncthreads();

    for (int base = 0; base < 2 * T_TOK; base += 256) {
        const int slot = base + tid;
        const int flag = (g_top_idx[slot] == e) ? 1 : 0;
        const unsigned bal = __ballot_sync(0xffffffffu, flag);
        const int pre = __popc(bal & ((1u << lane) - 1u));
        if (lane == 0) warp_tot[w] = __popc(bal);
        __syncthreads();
        int woff = 0;
        for (int i = 0; i < w; i++) woff += warp_tot[i];
        if (flag) g_rows[e * T_TOK + s_base + woff + pre] = slot;
        __syncthreads();
        if (tid == 0) {
            int tt = 0;
            for (int i = 0; i < 8; i++) tt += warp_tot[i];
            s_base += tt;
        }
        __syncthreads();
    }
    if (tid == 0) g_counts[e] = s_base;
}

// ============================================================================
// HMMA GEMM kernels. CTA tile 128x128, 8 warps (2M x 4N), warp tile 64x32.
// K chunks of 32 bf16, double-buffered. Rows padded to 80B (conflict-free ldsm).
// 3-term bf16 hi/lo split: hh + hl + lh.
// Stage layout: [Ah 10240][Al 10240][Bh 10240][Bl 10240] = 40960 B; 2 stages.
// ============================================================================
#define KC     32
#define ROWB   80
#define MATB   (128 * ROWB)          // 10240
#define STAGE  (4 * MATB)            // 40960
#define SMEM_DYN (2 * STAGE)         // 81920

// ---- Kernel 3: up GEMM + SiLU. B rows interleaved gate/up. grid (E*64, 8) ----
__global__ void __launch_bounds__(256, 1) up_gemm_mma(
    const float* __restrict__ x, const float* __restrict__ w13)
{
    const int e  = blockIdx.x >> 6;
    const int mt = blockIdx.x & 63;
    const int cnt = g_counts[e];
    const int m0 = mt * 128;
    if (m0 >= cnt) return;
    const int rcount = min(128, cnt - m0);
    const int ib = blockIdx.y * 64;                 // intermediate col base

    extern __shared__ char sm[];
    const u32 smu = smem_u32(sm);
    __shared__ int s_slot[128];
    __shared__ int s_tok[128];

    const int tid = threadIdx.x, lane = tid & 31, wid = tid >> 5;
    const int wm = wid >> 2, wn = wid & 3;

    if (tid < 128) {
        const int sl = g_rows[e * T_TOK + m0 + min(tid, rcount - 1)];
        s_slot[tid] = sl;
        s_tok[tid] = sl >> 1;
    }
    __syncthreads();

    const int r0t = tid >> 2, seg = tid & 3;
    float4 ra[4][2];

    auto gload = [&](int kc) {
        const int kof = kc * KC + seg * 8;
#pragma unroll
        for (int it = 0; it < 4; it++) {
            const int r = r0t + it * 64;
            const float* src;
            if (r < 128) {
                src = x + (size_t)s_tok[r] * H_DIM + kof;
            } else {
                const int q = r - 128;
                const int wrow = (q & 1) ? (512 + ib + (q >> 1)) : (ib + (q >> 1));
                src = w13 + ((size_t)e * 1024 + wrow) * H_DIM + kof;
            }
            ra[it][0] = __ldg((const float4*)src);
            ra[it][1] = __ldg((const float4*)src + 1);
        }
    };
    auto sstore = [&](int p) {
        const u32 st = smu + p * STAGE;
#pragma unroll
        for (int it = 0; it < 4; it++) {
            const int r = r0t + it * 64;
            uint4 hi, lo; cvt8(ra[it][0], ra[it][1], hi, lo);
            const u32 base = (r < 128) ? (st + r * ROWB)
                                       : (st + 2 * MATB + (r - 128) * ROWB);
            STS128U(base + seg * 16, hi);
            STS128U(base + MATB + seg * 16, lo);
        }
    };

    float acc[4][4][4];
#pragma unroll
    for (int i = 0; i < 4; i++)
#pragma unroll
        for (int j = 0; j < 4; j++)
#pragma unroll
            for (int q = 0; q < 4; q++) acc[i][j][q] = 0.f;

    gload(0);
    const u32 lrow = (u32)(lane & 15) * ROWB + (u32)((lane >> 4) << 4);

#pragma unroll 1
    for (int c = 0; c < 32; c++) {
        const int p = c & 1;
        sstore(p);
        __syncthreads();
        if (c + 1 < 32) gload(c + 1);
        const u32 aB = smu + p * STAGE + (u32)(wm * 64) * ROWB + lrow;
        const u32 bB = smu + p * STAGE + 2 * MATB + (u32)(wn * 32) * ROWB + lrow;
#pragma unroll
        for (int kk = 0; kk < 2; kk++) {
            const u32 ko = kk * 32;
            u32 ah[4][4], al[4][4], bh[2][4], bl[2][4];
#pragma unroll
            for (int mi = 0; mi < 4; mi++) {
                ldsm4(ah[mi][0], ah[mi][1], ah[mi][2], ah[mi][3], aB + mi * 16 * ROWB + ko);
                ldsm4(al[mi][0], al[mi][1], al[mi][2], al[mi][3], aB + MATB + mi * 16 * ROWB + ko);
            }
            ldsm4(bh[0][0], bh[0][1], bh[0][2], bh[0][3], bB + ko);
            ldsm4(bh[1][0], bh[1][1], bh[1][2], bh[1][3], bB + 16 * ROWB + ko);
            ldsm4(bl[0][0], bl[0][1], bl[0][2], bl[0][3], bB + MATB + ko);
            ldsm4(bl[1][0], bl[1][1], bl[1][2], bl[1][3], bB + MATB + 16 * ROWB + ko);
#pragma unroll
            for (int mi = 0; mi < 4; mi++)
#pragma unroll
                for (int nj = 0; nj < 4; nj++) {
                    const int g = nj >> 1, o = nj & 1;
                    mma_bf16(acc[mi][nj], ah[mi], bh[g][o], bh[g][o + 2]);
                    mma_bf16(acc[mi][nj], ah[mi], bl[g][o], bl[g][o + 2]);
                    mma_bf16(acc[mi][nj], al[mi], bh[g][o], bh[g][o + 2]);
                }
        }
    }

    // epilogue: acc pair (c0,c1) = (gate, up) of icol; rows m, m+8
    const int qr = lane >> 2, qc = lane & 3;
#pragma unroll
    for (int mi = 0; mi < 4; mi++) {
        const int mlo = wm * 64 + mi * 16 + qr;
#pragma unroll
        for (int nj = 0; nj < 4; nj++) {
            const int icol = ib + wn * 16 + nj * 4 + qc;
            const float* a4 = acc[mi][nj];
            if (mlo < rcount) {
                const float g = a4[0], u = a4[1];
                g_act[(size_t)s_slot[mlo] * I_DIM + icol] = g / (1.f + __expf(-g)) * u;
            }
            if (mlo + 8 < rcount) {
                const float g = a4[2], u = a4[3];
                g_act[(size_t)s_slot[mlo + 8] * I_DIM + icol] = g / (1.f + __expf(-g)) * u;
            }
        }
    }
}

// ---- Kernel 4: down GEMM, scale by gate weight * 2.5. grid (E*64, 8) ----
__global__ void __launch_bounds__(256, 1) down_gemm_mma(const float* __restrict__ w2)
{
    const int e  = blockIdx.x >> 6;
    const int mt = blockIdx.x & 63;
    const int cnt = g_counts[e];
    const int m0 = mt * 128;
    if (m0 >= cnt) return;
    const int rcount = min(128, cnt - m0);
    const int hb = blockIdx.y * 128;

    extern __shared__ char sm[];
    const u32 smu = smem_u32(sm);
    __shared__ int   s_slot[128];
    __shared__ float s_wt[128];

    const int tid = threadIdx.x, lane = tid & 31, wid = tid >> 5;
    const int wm = wid >> 2, wn = wid & 3;

    if (tid < 128) {
        const int sl = g_rows[e * T_TOK + m0 + min(tid, rcount - 1)];
        s_slot[tid] = sl;
        s_wt[tid] = g_top_w[sl] * SCALE_F;
    }
    __syncthreads();

    const int r0t = tid >> 2, seg = tid & 3;
    float4 ra[4][2];

    auto gload = [&](int kc) {
        const int kof = kc * KC + seg * 8;
#pragma unroll
        for (int it = 0; it < 4; it++) {
            const int r = r0t + it * 64;
            const float* src;
            if (r < 128) src = g_act + (size_t)s_slot[r] * I_DIM + kof;
            else         src = w2 + ((size_t)e * H_DIM + hb + (r - 128)) * I_DIM + kof;
            ra[it][0] = __ldg((const float4*)src);
            ra[it][1] = __ldg((const float4*)src + 1);
        }
    };
    auto sstore = [&](int p) {
        const u32 st = smu + p * STAGE;
#pragma unroll
        for (int it = 0; it < 4; it++) {
            const int r = r0t + it * 64;
            uint4 hi, lo; cvt8(ra[it][0], ra[it][1], hi, lo);
            const u32 base = (r < 128) ? (st + r * ROWB)
                                       : (st + 2 * MATB + (r - 128) * ROWB);
            STS128U(base + seg * 16, hi);
            STS128U(base + MATB + seg * 16, lo);
        }
    };

    float acc[4][4][4];
#pragma unroll
    for (int i = 0; i < 4; i++)
#pragma unroll
        for (int j = 0; j < 4; j++)
#pragma unroll
            for (int q = 0; q < 4; q++) acc[i][j][q] = 0.f;

    gload(0);
    const u32 lrow = (u32)(lane & 15) * ROWB + (u32)((lane >> 4) << 4);

#pragma unroll 1
    for (int c = 0; c < 16; c++) {
        const int p = c & 1;
        sstore(p);
        __syncthreads();
        if (c + 1 < 16) gload(c + 1);
        const u32 aB = smu + p * STAGE + (u32)(wm * 64) * ROWB + lrow;
        const u32 bB = smu + p * STAGE + 2 * MATB + (u32)(wn * 32) * ROWB + lrow;
#pragma unroll
        for (int kk = 0; kk < 2; kk++) {
            const u32 ko = kk * 32;
            u32 ah[4][4], al[4][4], bh[2][4], bl[2][4];
#pragma unroll
            for (int mi = 0; mi < 4; mi++) {
                ldsm4(ah[mi][0], ah[mi][1], ah[mi][2], ah[mi][3], aB + mi * 16 * ROWB + ko);
                ldsm4(al[mi][0], al[mi][1], al[mi][2], al[mi][3], aB + MATB + mi * 16 * ROWB + ko);
            }
            ldsm4(bh[0][0], bh[0][1], bh[0][2], bh[0][3], bB + ko);
            ldsm4(bh[1][0], bh[1][1], bh[1][2], bh[1][3], bB + 16 * ROWB + ko);
            ldsm4(bl[0][0], bl[0][1], bl[0][2], bl[0][3], bB + MATB + ko);
            ldsm4(bl[1][0], bl[1][1], bl[1][2], bl[1][3], bB + MATB + 16 * ROWB + ko);
#pragma unroll
            for (int mi = 0; mi < 4; mi++)
#pragma unroll
                for (int nj = 0; nj < 4; nj++) {
                    const int g = nj >> 1, o = nj & 1;
                    mma_bf16(acc[mi][nj], ah[mi], bh[g][o], bh[g][o + 2]);
                    mma_bf16(acc[mi][nj], ah[mi], bl[g][o], bl[g][o + 2]);
                    mma_bf16(acc[mi][nj], al[mi], bh[g][o], bh[g][o + 2]);
                }
        }
    }

    const int qr = lane >> 2, qc = lane & 3;
#pragma unroll
    for (int mi = 0; mi < 4; mi++) {
        const int mlo = wm * 64 + mi * 16 + qr;
#pragma unroll
        for (int nj = 0; nj < 4; nj++) {
            const int n0 = hb + wn * 32 + nj * 8 + 2 * qc;
            const float* a4 = acc[mi][nj];
            if (mlo < rcount) {
                const float wt = s_wt[mlo];
                float2 v; v.x = wt * a4[0]; v.y = wt * a4[1];
                *(float2*)(g_y + (size_t)s_slot[mlo] * H_DIM + n0) = v;
            }
            if (mlo + 8 < rcount) {
                const float wt = s_wt[mlo + 8];
                float2 v; v.x = wt * a4[2]; v.y = wt * a4[3];
                *(float2*)(g_y + (size_t)s_slot[mlo + 8] * H_DIM + n0) = v;
            }
        }
    }
}

// ============================================================================
// Kernel 5: finalize (proven)
// ============================================================================
__global__ void __launch_bounds__(256) finalize_kernel(
    const float* __restrict__ x, float* __restrict__ out)
{
    const int t = blockIdx.x;
    const float zs = g_zero_scale[t];
    const bool r0 = g_top_idx[2 * t]     < E_EXP;
    const bool r1 = g_top_idx[2 * t + 1] < E_EXP;
    const int h = threadIdx.x * 4;

    float4 xv = *(const float4*)(x + (size_t)t * H_DIM + h);
    float4 o;
    o.x = zs * xv.x; o.y = zs * xv.y; o.z = zs * xv.z; o.w = zs * xv.w;
    if (r0) {
        float4 y = *(const float4*)(g_y + (size_t)(2 * t) * H_DIM + h);
        o.x += y.x; o.y += y.y; o.z += y.z; o.w += y.w;
    }
    if (r1) {
        float4 y = *(const float4*)(g_y + (size_t)(2 * t + 1) * H_DIM + h);
        o.x += y.x; o.y += y.y; o.z += y.z; o.w += y.w;
    }
    *(float4*)(out + (size_t)t * H_DIM + h) = o;
}

// ============================================================================
// launch
// ============================================================================
extern "C" void kernel_launch(void* const* d_in, const int* in_sizes, int n_in,
                              void* d_out, int out_size)
{
    const float* x    = (const float*)d_in[0];
    const float* rw   = (const float*)d_in[1];
    const float* bias = (const float*)d_in[2];
    const float* w13  = (const float*)d_in[3];
    const float* w2   = (const float*)d_in[4];
    float* out = (float*)d_out;

    cudaFuncSetAttribute(up_gemm_mma,   cudaFuncAttributeMaxDynamicSharedMemorySize, SMEM_DYN);
    cudaFuncSetAttribute(down_gemm_mma, cudaFuncAttributeMaxDynamicSharedMemorySize, SMEM_DYN);

    router_kernel<<<T_TOK / 8, 256>>>(x, rw, bias);
    build_lists_kernel<<<E_EXP, 256>>>();

    dim3 gu(E_EXP * 64, 8);
    up_gemm_mma<<<gu, 256, SMEM_DYN>>>(x, w13);

    dim3 gd(E_EXP * 64, 8);
    down_gemm_mma<<<gd, 256, SMEM_DYN>>>(w2);

    finalize_kernel<<<T_TOK, 256>>>(x, out);
}

// round 5
// speedup vs baseline: 2.9276x; 1.2229x over previous
#include <cuda_runtime.h>
#include <cuda_fp16.h>
#include <cstdint>

#define T_TOK   8192
#define H_DIM   1024
#define I_DIM   512
#define E_EXP   8
#define EZ_EXP  12
#define SCALE_F 2.5f

typedef unsigned int u32;
typedef unsigned long long u64;

// ---------------- scratch (device globals; no allocation) ----------------
__device__ int    g_top_idx[T_TOK * 2];
__device__ float  g_top_w[T_TOK * 2];
__device__ float  g_zero_scale[T_TOK];
__device__ int    g_counts[E_EXP];
__device__ int    g_rows[E_EXP * T_TOK];
__device__ __half g_xh[(size_t)T_TOK * H_DIM];            // x hi
__device__ __half g_xl[(size_t)T_TOK * H_DIM];            // x lo residual
__device__ __half g_w13h[(size_t)E_EXP * 2 * I_DIM * H_DIM]; // fp16(w13)
__device__ __half g_w2h[(size_t)E_EXP * H_DIM * I_DIM];      // fp16(w2)
__device__ __half g_acth[(size_t)T_TOK * 2 * I_DIM];      // act hi (per slot)
__device__ __half g_actl[(size_t)T_TOK * 2 * I_DIM];      // act lo
__device__ float  g_y[(size_t)T_TOK * 2 * H_DIM];         // per-slot down output

// ---------------- helpers ----------------
__device__ __forceinline__ u32 smem_u32(const void* p) {
    u32 a;
    asm("{ .reg .u64 t; cvta.to.shared.u64 t, %1; cvt.u32.u64 %0, t; }" : "=r"(a) : "l"(p));
    return a;
}

#define CPA16(dst, src) \
    asm volatile("{.reg .u64 g; cvta.to.global.u64 g, %1; cp.async.cg.shared.global [%0], [g], 16;}\n" \
                 :: "r"((u32)(dst)), "l"(src) : "memory")
#define CPCOMMIT() asm volatile("cp.async.commit_group;" ::: "memory")
#define CPWAIT1()  asm volatile("cp.async.wait_group 1;" ::: "memory")

__device__ __forceinline__ void ldsm4(u32& r0, u32& r1, u32& r2, u32& r3, u32 addr) {
    asm volatile("ldmatrix.sync.aligned.m8n8.x4.shared.b16 {%0,%1,%2,%3}, [%4];"
                 : "=r"(r0), "=r"(r1), "=r"(r2), "=r"(r3) : "r"(addr));
}

__device__ __forceinline__ void mma_f16(float* d, const u32* a, u32 b0, u32 b1) {
    asm volatile("mma.sync.aligned.m16n8k16.row.col.f32.f16.f16.f32 "
        "{%0,%1,%2,%3}, {%4,%5,%6,%7}, {%8,%9}, {%0,%1,%2,%3};"
        : "+f"(d[0]), "+f"(d[1]), "+f"(d[2]), "+f"(d[3])
        : "r"(a[0]), "r"(a[1]), "r"(a[2]), "r"(a[3]), "r"(b0), "r"(b1));
}

// ============================================================================
// Conversion kernels (one-time per launch)
// ============================================================================
__global__ void __launch_bounds__(256) cvt_x_kernel(const float* __restrict__ x)
{
    const size_t i = ((size_t)blockIdx.x * 256 + threadIdx.x) * 4;
    const float4 v = *(const float4*)(x + i);
    const __half h0 = __float2half_rn(v.x), h1 = __float2half_rn(v.y);
    const __half h2 = __float2half_rn(v.z), h3 = __float2half_rn(v.w);
    *(__half2*)(g_xh + i)     = __halves2half2(h0, h1);
    *(__half2*)(g_xh + i + 2) = __halves2half2(h2, h3);
    const __half l0 = __float2half_rn(v.x - __half2float(h0));
    const __half l1 = __float2half_rn(v.y - __half2float(h1));
    const __half l2 = __float2half_rn(v.z - __half2float(h2));
    const __half l3 = __float2half_rn(v.w - __half2float(h3));
    *(__half2*)(g_xl + i)     = __halves2half2(l0, l1);
    *(__half2*)(g_xl + i + 2) = __halves2half2(l2, l3);
}

#define W13_ELEMS ((size_t)E_EXP * 2 * I_DIM * H_DIM)   // 8388608
__global__ void __launch_bounds__(256) cvt_w_kernel(
    const float* __restrict__ w13, const float* __restrict__ w2)
{
    const size_t gid = (size_t)blockIdx.x * 256 + threadIdx.x;
    const float* src; __half* dst; size_t off;
    if (gid < W13_ELEMS / 4) { src = w13; dst = g_w13h; off = gid * 4; }
    else { src = w2; dst = g_w2h; off = (gid - W13_ELEMS / 4) * 4; }
    const float4 v = *(const float4*)(src + off);
    *(__half2*)(dst + off)     = __halves2half2(__float2half_rn(v.x), __float2half_rn(v.y));
    *(__half2*)(dst + off + 2) = __halves2half2(__float2half_rn(v.z), __float2half_rn(v.w));
}

// ============================================================================
// Kernel: router (proven)
// ============================================================================
__global__ void __launch_bounds__(256) router_kernel(
    const float* __restrict__ x, const float* __restrict__ rw, const float* __restrict__ bias)
{
    __shared__ float srw[EZ_EXP * H_DIM];
    const int tid = threadIdx.x;
    for (int i = tid; i < EZ_EXP * H_DIM; i += 256) srw[i] = rw[i];
    __syncthreads();

    const int warp = tid >> 5, lane = tid & 31;
    const int t = blockIdx.x * 8 + warp;
    const float* xr = x + (size_t)t * H_DIM;

    float xv[32];
#pragma unroll
    for (int j = 0; j < 32; j++) xv[j] = xr[lane + 32 * j];

    float logits[EZ_EXP];
#pragma unroll
    for (int e = 0; e < EZ_EXP; e++) {
        const float* wr = srw + e * H_DIM;
        float acc = 0.f;
#pragma unroll
        for (int j = 0; j < 32; j++) acc += xv[j] * wr[lane + 32 * j];
#pragma unroll
        for (int off = 16; off; off >>= 1) acc += __shfl_xor_sync(0xffffffffu, acc, off);
        logits[e] = acc;
    }

    if (lane == 0) {
        float mx = logits[0];
#pragma unroll
        for (int e = 1; e < EZ_EXP; e++) mx = fmaxf(mx, logits[e]);
        float sc[EZ_EXP], s = 0.f;
#pragma unroll
        for (int e = 0; e < EZ_EXP; e++) { sc[e] = __expf(logits[e] - mx); s += sc[e]; }
        const float inv = 1.f / s;
        float bsc[EZ_EXP];
#pragma unroll
        for (int e = 0; e < EZ_EXP; e++) { sc[e] *= inv; bsc[e] = sc[e] + bias[e]; }

        int i1 = 0;
#pragma unroll
        for (int e = 1; e < EZ_EXP; e++) if (bsc[e] > bsc[i1]) i1 = e;
        int i2 = (i1 == 0) ? 1 : 0;
#pragma unroll
        for (int e = 0; e < EZ_EXP; e++) if (e != i1 && bsc[e] > bsc[i2]) i2 = e;

        const float w1 = sc[i1], w2v = sc[i2];
        g_top_idx[2 * t] = i1;  g_top_idx[2 * t + 1] = i2;
        g_top_w[2 * t] = w1;    g_top_w[2 * t + 1] = w2v;
        float zs = 0.f;
        if (i1 >= E_EXP) zs += w1;
        if (i2 >= E_EXP) zs += w2v;
        g_zero_scale[t] = zs;
    }
}

// ============================================================================
// Kernel: stable per-expert compaction (proven, deterministic)
// ============================================================================
__global__ void __launch_bounds__(256) build_lists_kernel()
{
    const int e = blockIdx.x;
    const int tid = threadIdx.x;
    const int lane = tid & 31, w = tid >> 5;
    __shared__ int warp_tot[8];
    __shared__ int s_base;
    if (tid == 0) s_base = 0;
    __syncthreads();

    for (int base = 0; base < 2 * T_TOK; base += 256) {
        const int slot = base + tid;
        const int flag = (g_top_idx[slot] == e) ? 1 : 0;
        const unsigned bal = __ballot_sync(0xffffffffu, flag);
        const int pre = __popc(bal & ((1u << lane) - 1u));
        if (lane == 0) warp_tot[w] = __popc(bal);
        __syncthreads();
        int woff = 0;
        for (int i = 0; i < w; i++) woff += warp_tot[i];
        if (flag) g_rows[e * T_TOK + s_base + woff + pre] = slot;
        __syncthreads();
        if (tid == 0) {
            int tt = 0;
            for (int i = 0; i < 8; i++) tt += warp_tot[i];
            s_base += tt;
        }
        __syncthreads();
    }
    if (tid == 0) g_counts[e] = s_base;
}

// ============================================================================
// HMMA GEMMs, 2-term fp16 (A = hi/lo split, B = fp16 single).
// CTA tile 128x128, 8 warps (2M x 4N), warp tile 64x32, K chunk 32.
// cp.async 3-stage pipeline; smem rows padded to 80B (conflict-free ldmatrix).
// Stage: [Ah 10240][Al 10240][B 10240] = 30720 B.
// ============================================================================
#define ROWB   80
#define MATB   (128 * ROWB)       // 10240
#define STAGE  (3 * MATB)         // 30720
#define NSTG   3
#define SMEM_DYN (NSTG * STAGE)   // 92160

// ---- up GEMM + SiLU: A = x(hi/lo), B = w13 interleaved gate/up. grid (E*64, 8)
__global__ void __launch_bounds__(256, 2) up_gemm_mma()
{
    const int e  = blockIdx.x >> 6;
    const int mt = blockIdx.x & 63;
    const int cnt = g_counts[e];
    const int m0 = mt * 128;
    if (m0 >= cnt) return;
    const int rcount = min(128, cnt - m0);
    const int ib = blockIdx.y * 64;

    extern __shared__ char sm[];
    const u32 smu = smem_u32(sm);
    __shared__ int s_slot[128];
    __shared__ int s_tok[128];

    const int tid = threadIdx.x, lane = tid & 31, wid = tid >> 5;
    const int wm = wid >> 2, wn = wid & 3;

    if (tid < 128) {
        const int sl = g_rows[e * T_TOK + m0 + min(tid, rcount - 1)];
        s_slot[tid] = sl;
        s_tok[tid] = sl >> 1;
    }
    __syncthreads();

    // per-thread 6 cp.async descriptors (16B each): 3 matrices x 512 chunks / 256 thr
    const char* srcs[6];
    u32 dsts[6];
#pragma unroll
    for (int t = 0; t < 6; t++) {
        const int idx = tid + t * 256;
        const int mat = idx >> 9, rr = (idx >> 2) & 127, ch = idx & 3;
        dsts[t] = (u32)(mat * MATB + rr * ROWB + ch * 16);
        if (mat == 0)      srcs[t] = (const char*)(g_xh + (size_t)s_tok[rr] * H_DIM + ch * 8);
        else if (mat == 1) srcs[t] = (const char*)(g_xl + (size_t)s_tok[rr] * H_DIM + ch * 8);
        else {
            const int wrow = (rr & 1) ? (512 + ib + (rr >> 1)) : (ib + (rr >> 1));
            srcs[t] = (const char*)(g_w13h + ((size_t)e * 1024 + wrow) * H_DIM + ch * 8);
        }
    }

    float acc[4][4][4];
#pragma unroll
    for (int i = 0; i < 4; i++)
#pragma unroll
        for (int j = 0; j < 4; j++)
#pragma unroll
            for (int q = 0; q < 4; q++) acc[i][j][q] = 0.f;

    // prologue: stages 0,1
#pragma unroll
    for (int t = 0; t < 6; t++) CPA16(smu + 0 * STAGE + dsts[t], srcs[t] + 0 * 64);
    CPCOMMIT();
#pragma unroll
    for (int t = 0; t < 6; t++) CPA16(smu + 1 * STAGE + dsts[t], srcs[t] + 1 * 64);
    CPCOMMIT();

    const u32 lrow = (u32)(lane & 15) * ROWB + (u32)((lane >> 4) << 4);

#pragma unroll 1
    for (int c = 0; c < 32; c++) {
        const int p = c % NSTG;
        CPWAIT1();
        __syncthreads();
        if (c + 2 < 32) {
            const u32 sb = smu + ((c + 2) % NSTG) * STAGE;
            const size_t go = (size_t)(c + 2) * 64;
#pragma unroll
            for (int t = 0; t < 6; t++) CPA16(sb + dsts[t], srcs[t] + go);
        }
        CPCOMMIT();

        const u32 aB = smu + p * STAGE + (u32)(wm * 64) * ROWB + lrow;
        const u32 bB = smu + p * STAGE + 2 * MATB + (u32)(wn * 32) * ROWB + lrow;
#pragma unroll
        for (int kk = 0; kk < 2; kk++) {
            const u32 ko = kk * 32;
            u32 ah[4][4], al[4][4], b[2][4];
#pragma unroll
            for (int mi = 0; mi < 4; mi++) {
                ldsm4(ah[mi][0], ah[mi][1], ah[mi][2], ah[mi][3], aB + mi * 16 * ROWB + ko);
                ldsm4(al[mi][0], al[mi][1], al[mi][2], al[mi][3], aB + MATB + mi * 16 * ROWB + ko);
            }
            ldsm4(b[0][0], b[0][1], b[0][2], b[0][3], bB + ko);
            ldsm4(b[1][0], b[1][1], b[1][2], b[1][3], bB + 16 * ROWB + ko);
#pragma unroll
            for (int mi = 0; mi < 4; mi++)
#pragma unroll
                for (int nj = 0; nj < 4; nj++) {
                    const int g = nj >> 1, o = nj & 1;
                    mma_f16(acc[mi][nj], ah[mi], b[g][o], b[g][o + 2]);
                    mma_f16(acc[mi][nj], al[mi], b[g][o], b[g][o + 2]);
                }
        }
    }

    // epilogue: (c0,c1)/(c2,c3) = (gate, up) for rows m, m+8; write act hi/lo fp16
    const int qr = lane >> 2, qc = lane & 3;
#pragma unroll
    for (int mi = 0; mi < 4; mi++) {
        const int mlo = wm * 64 + mi * 16 + qr;
#pragma unroll
        for (int nj = 0; nj < 4; nj++) {
            const int icol = ib + wn * 16 + nj * 4 + qc;
            const float* a4 = acc[mi][nj];
            if (mlo < rcount) {
                const float g = a4[0], u = a4[1];
                const float act = g / (1.f + __expf(-g)) * u;
                const __half h = __float2half_rn(act);
                const size_t o = (size_t)s_slot[mlo] * I_DIM + icol;
                g_acth[o] = h;
                g_actl[o] = __float2half_rn(act - __half2float(h));
            }
            if (mlo + 8 < rcount) {
                const float g = a4[2], u = a4[3];
                const float act = g / (1.f + __expf(-g)) * u;
                const __half h = __float2half_rn(act);
                const size_t o = (size_t)s_slot[mlo + 8] * I_DIM + icol;
                g_acth[o] = h;
                g_actl[o] = __float2half_rn(act - __half2float(h));
            }
        }
    }
}

// ---- down GEMM: A = act(hi/lo), B = w2. K=512 (16 chunks). grid (E*64, 8) ----
__global__ void __launch_bounds__(256, 2) down_gemm_mma()
{
    const int e  = blockIdx.x >> 6;
    const int mt = blockIdx.x & 63;
    const int cnt = g_counts[e];
    const int m0 = mt * 128;
    if (m0 >= cnt) return;
    const int rcount = min(128, cnt - m0);
    const int hb = blockIdx.y * 128;

    extern __shared__ char sm[];
    const u32 smu = smem_u32(sm);
    __shared__ int   s_slot[128];
    __shared__ float s_wt[128];

    const int tid = threadIdx.x, lane = tid & 31, wid = tid >> 5;
    const int wm = wid >> 2, wn = wid & 3;

    if (tid < 128) {
        const int sl = g_rows[e * T_TOK + m0 + min(tid, rcount - 1)];
        s_slot[tid] = sl;
        s_wt[tid] = g_top_w[sl] * SCALE_F;
    }
    __syncthreads();

    const char* srcs[6];
    u32 dsts[6];
#pragma unroll
    for (int t = 0; t < 6; t++) {
        const int idx = tid + t * 256;
        const int mat = idx >> 9, rr = (idx >> 2) & 127, ch = idx & 3;
        dsts[t] = (u32)(mat * MATB + rr * ROWB + ch * 16);
        if (mat == 0)      srcs[t] = (const char*)(g_acth + (size_t)s_slot[rr] * I_DIM + ch * 8);
        else if (mat == 1) srcs[t] = (const char*)(g_actl + (size_t)s_slot[rr] * I_DIM + ch * 8);
        else srcs[t] = (const char*)(g_w2h + ((size_t)e * H_DIM + hb + rr) * I_DIM + ch * 8);
    }

    float acc[4][4][4];
#pragma unroll
    for (int i = 0; i < 4; i++)
#pragma unroll
        for (int j = 0; j < 4; j++)
#pragma unroll
            for (int q = 0; q < 4; q++) acc[i][j][q] = 0.f;

#pragma unroll
    for (int t = 0; t < 6; t++) CPA16(smu + 0 * STAGE + dsts[t], srcs[t] + 0 * 64);
    CPCOMMIT();
#pragma unroll
    for (int t = 0; t < 6; t++) CPA16(smu + 1 * STAGE + dsts[t], srcs[t] + 1 * 64);
    CPCOMMIT();

    const u32 lrow = (u32)(lane & 15) * ROWB + (u32)((lane >> 4) << 4);

#pragma unroll 1
    for (int c = 0; c < 16; c++) {
        const int p = c % NSTG;
        CPWAIT1();
        __syncthreads();
        if (c + 2 < 16) {
            const u32 sb = smu + ((c + 2) % NSTG) * STAGE;
            const size_t go = (size_t)(c + 2) * 64;
#pragma unroll
            for (int t = 0; t < 6; t++) CPA16(sb + dsts[t], srcs[t] + go);
        }
        CPCOMMIT();

        const u32 aB = smu + p * STAGE + (u32)(wm * 64) * ROWB + lrow;
        const u32 bB = smu + p * STAGE + 2 * MATB + (u32)(wn * 32) * ROWB + lrow;
#pragma unroll
        for (int kk = 0; kk < 2; kk++) {
            const u32 ko = kk * 32;
            u32 ah[4][4], al[4][4], b[2][4];
#pragma unroll
            for (int mi = 0; mi < 4; mi++) {
                ldsm4(ah[mi][0], ah[mi][1], ah[mi][2], ah[mi][3], aB + mi * 16 * ROWB + ko);
                ldsm4(al[mi][0], al[mi][1], al[mi][2], al[mi][3], aB + MATB + mi * 16 * ROWB + ko);
            }
            ldsm4(b[0][0], b[0][1], b[0][2], b[0][3], bB + ko);
            ldsm4(b[1][0], b[1][1], b[1][2], b[1][3], bB + 16 * ROWB + ko);
#pragma unroll
            for (int mi = 0; mi < 4; mi++)
#pragma unroll
                for (int nj = 0; nj < 4; nj++) {
                    const int g = nj >> 1, o = nj & 1;
                    mma_f16(acc[mi][nj], ah[mi], b[g][o], b[g][o + 2]);
                    mma_f16(acc[mi][nj], al[mi], b[g][o], b[g][o + 2]);
                }
        }
    }

    const int qr = lane >> 2, qc = lane & 3;
#pragma unroll
    for (int mi = 0; mi < 4; mi++) {
        const int mlo = wm * 64 + mi * 16 + qr;
#pragma unroll
        for (int nj = 0; nj < 4; nj++) {
            const int n0 = hb + wn * 32 + nj * 8 + 2 * qc;
            const float* a4 = acc[mi][nj];
            if (mlo < rcount) {
                const float wt = s_wt[mlo];
                float2 v; v.x = wt * a4[0]; v.y = wt * a4[1];
                *(float2*)(g_y + (size_t)s_slot[mlo] * H_DIM + n0) = v;
            }
            if (mlo + 8 < rcount) {
                const float wt = s_wt[mlo + 8];
                float2 v; v.x = wt * a4[2]; v.y = wt * a4[3];
                *(float2*)(g_y + (size_t)s_slot[mlo + 8] * H_DIM + n0) = v;
            }
        }
    }
}

// ============================================================================
// Kernel: finalize (proven)
// ============================================================================
__global__ void __launch_bounds__(256) finalize_kernel(
    const float* __restrict__ x, float* __restrict__ out)
{
    const int t = blockIdx.x;
    const float zs = g_zero_scale[t];
    const bool r0 = g_top_idx[2 * t]     < E_EXP;
    const bool r1 = g_top_idx[2 * t + 1] < E_EXP;
    const int h = threadIdx.x * 4;

    float4 xv = *(const float4*)(x + (size_t)t * H_DIM + h);
    float4 o;
    o.x = zs * xv.x; o.y = zs * xv.y; o.z = zs * xv.z; o.w = zs * xv.w;
    if (r0) {
        float4 y = *(const float4*)(g_y + (size_t)(2 * t) * H_DIM + h);
        o.x += y.x; o.y += y.y; o.z += y.z; o.w += y.w;
    }
    if (r1) {
        float4 y = *(const float4*)(g_y + (size_t)(2 * t + 1) * H_DIM + h);
        o.x += y.x; o.y += y.y; o.z += y.z; o.w += y.w;
    }
    *(float4*)(out + (size_t)t * H_DIM + h) = o;
}

// ============================================================================
// launch
// ============================================================================
extern "C" void kernel_launch(void* const* d_in, const int* in_sizes, int n_in,
                              void* d_out, int out_size)
{
    const float* x    = (const float*)d_in[0];
    const float* rw   = (const float*)d_in[1];
    const float* bias = (const float*)d_in[2];
    const float* w13  = (const float*)d_in[3];
    const float* w2   = (const float*)d_in[4];
    float* out = (float*)d_out;

    cudaFuncSetAttribute(up_gemm_mma,   cudaFuncAttributeMaxDynamicSharedMemorySize, SMEM_DYN);
    cudaFuncSetAttribute(down_gemm_mma, cudaFuncAttributeMaxDynamicSharedMemorySize, SMEM_DYN);

    cvt_x_kernel<<<T_TOK * H_DIM / 1024, 256>>>(x);
    cvt_w_kernel<<<(W13_ELEMS + (size_t)E_EXP * H_DIM * I_DIM) / 1024, 256>>>(w13, w2);
    router_kernel<<<T_TOK / 8, 256>>>(x, rw, bias);
    build_lists_kernel<<<E_EXP, 256>>>();

    dim3 gu(E_EXP * 64, 8);
    up_gemm_mma<<<gu, 256, SMEM_DYN>>>();

    dim3 gd(E_EXP * 64, 8);
    down_gemm_mma<<<gd, 256, SMEM_DYN>>>();

    finalize_kernel<<<T_TOK, 256>>>(x, out);
}

// round 6
// speedup vs baseline: 5.0600x; 1.7284x over previous
#include <cuda_runtime.h>
#include <cuda_fp16.h>
#include <cstdint>

#define T_TOK   8192
#define H_DIM   1024
#define I_DIM   512
#define E_EXP   8
#define EZ_EXP  12
#define SCALE_F 2.5f

typedef unsigned int u32;
typedef unsigned long long u64;

// ---------------- scratch (device globals; no allocation) ----------------
__device__ int    g_top_idx[T_TOK * 2];
__device__ float  g_top_w[T_TOK * 2];
__device__ float  g_zero_scale[T_TOK];
__device__ int    g_counts[E_EXP];
__device__ int    g_blk[E_EXP][16];
__device__ int    g_rows[E_EXP * T_TOK];
__device__ __half g_xh[(size_t)T_TOK * H_DIM];
__device__ __half g_w13h[(size_t)E_EXP * 2 * I_DIM * H_DIM];
__device__ __half g_w2h[(size_t)E_EXP * H_DIM * I_DIM];
__device__ __half g_acth[(size_t)T_TOK * 2 * I_DIM];
__device__ float  g_y[(size_t)T_TOK * 2 * H_DIM];

// ---------------- helpers ----------------
__device__ __forceinline__ u32 smem_u32(const void* p) {
    u32 a;
    asm("{ .reg .u64 t; cvta.to.shared.u64 t, %1; cvt.u32.u64 %0, t; }" : "=r"(a) : "l"(p));
    return a;
}

#define CPA16(dst, src) \
    asm volatile("{.reg .u64 g; cvta.to.global.u64 g, %1; cp.async.cg.shared.global [%0], [g], 16;}\n" \
                 :: "r"((u32)(dst)), "l"(src) : "memory")
#define CPCOMMIT() asm volatile("cp.async.commit_group;" ::: "memory")
#define CPWAIT2()  asm volatile("cp.async.wait_group 2;" ::: "memory")

__device__ __forceinline__ void ldsm4(u32& r0, u32& r1, u32& r2, u32& r3, u32 addr) {
    asm volatile("ldmatrix.sync.aligned.m8n8.x4.shared.b16 {%0,%1,%2,%3}, [%4];"
                 : "=r"(r0), "=r"(r1), "=r"(r2), "=r"(r3) : "r"(addr));
}

__device__ __forceinline__ void mma_f16(float* d, const u32* a, u32 b0, u32 b1) {
    asm volatile("mma.sync.aligned.m16n8k16.row.col.f32.f16.f16.f32 "
        "{%0,%1,%2,%3}, {%4,%5,%6,%7}, {%8,%9}, {%0,%1,%2,%3};"
        : "+f"(d[0]), "+f"(d[1]), "+f"(d[2]), "+f"(d[3])
        : "r"(a[0]), "r"(a[1]), "r"(a[2]), "r"(a[3]), "r"(b0), "r"(b1));
}

// ============================================================================
// weight conversion (one-time)
// ============================================================================
#define W13_ELEMS ((size_t)E_EXP * 2 * I_DIM * H_DIM)
__global__ void __launch_bounds__(256) cvt_w_kernel(
    const float* __restrict__ w13, const float* __restrict__ w2)
{
    const size_t gid = (size_t)blockIdx.x * 256 + threadIdx.x;
    const float* src; __half* dst; size_t off;
    if (gid < W13_ELEMS / 4) { src = w13; dst = g_w13h; off = gid * 4; }
    else { src = w2; dst = g_w2h; off = (gid - W13_ELEMS / 4) * 4; }
    const float4 v = *(const float4*)(src + off);
    *(__half2*)(dst + off)     = __halves2half2(__float2half_rn(v.x), __float2half_rn(v.y));
    *(__half2*)(dst + off + 2) = __halves2half2(__float2half_rn(v.z), __float2half_rn(v.w));
}

// ============================================================================
// router + fused x -> fp16 conversion
// ============================================================================
__global__ void __launch_bounds__(256) router_kernel(
    const float* __restrict__ x, const float* __restrict__ rw, const float* __restrict__ bias)
{
    __shared__ float srw[EZ_EXP * H_DIM];
    const int tid = threadIdx.x;
    for (int i = tid; i < EZ_EXP * H_DIM; i += 256) srw[i] = rw[i];
    __syncthreads();

    const int warp = tid >> 5, lane = tid & 31;
    const int t = blockIdx.x * 8 + warp;
    const float* xr = x + (size_t)t * H_DIM;

    float xv[32];
#pragma unroll
    for (int j = 0; j < 32; j++) xv[j] = xr[lane + 32 * j];

    // fused conversion to fp16
    __half* xhw = g_xh + (size_t)t * H_DIM;
#pragma unroll
    for (int j = 0; j < 32; j++) xhw[lane + 32 * j] = __float2half_rn(xv[j]);

    float logits[EZ_EXP];
#pragma unroll
    for (int e = 0; e < EZ_EXP; e++) {
        const float* wr = srw + e * H_DIM;
        float acc = 0.f;
#pragma unroll
        for (int j = 0; j < 32; j++) acc += xv[j] * wr[lane + 32 * j];
#pragma unroll
        for (int off = 16; off; off >>= 1) acc += __shfl_xor_sync(0xffffffffu, acc, off);
        logits[e] = acc;
    }

    if (lane == 0) {
        float mx = logits[0];
#pragma unroll
        for (int e = 1; e < EZ_EXP; e++) mx = fmaxf(mx, logits[e]);
        float sc[EZ_EXP], s = 0.f;
#pragma unroll
        for (int e = 0; e < EZ_EXP; e++) { sc[e] = __expf(logits[e] - mx); s += sc[e]; }
        const float inv = 1.f / s;
        float bsc[EZ_EXP];
#pragma unroll
        for (int e = 0; e < EZ_EXP; e++) { sc[e] *= inv; bsc[e] = sc[e] + bias[e]; }

        int i1 = 0;
#pragma unroll
        for (int e = 1; e < EZ_EXP; e++) if (bsc[e] > bsc[i1]) i1 = e;
        int i2 = (i1 == 0) ? 1 : 0;
#pragma unroll
        for (int e = 0; e < EZ_EXP; e++) if (e != i1 && bsc[e] > bsc[i2]) i2 = e;

        const float w1 = sc[i1], w2v = sc[i2];
        g_top_idx[2 * t] = i1;  g_top_idx[2 * t + 1] = i2;
        g_top_w[2 * t] = w1;    g_top_w[2 * t + 1] = w2v;
        float zs = 0.f;
        if (i1 >= E_EXP) zs += w1;
        if (i2 >= E_EXP) zs += w2v;
        g_zero_scale[t] = zs;
    }
}

// ============================================================================
// parallel deterministic list build: count -> scan+stable scatter
// ============================================================================
__global__ void __launch_bounds__(256) count_kernel()
{
    const int e = blockIdx.x, j = blockIdx.y;
    const int tid = threadIdx.x, lane = tid & 31, w = tid >> 5;
    __shared__ int wsum[8];
    int c = 0;
#pragma unroll
    for (int it = 0; it < 4; it++)
        c += (g_top_idx[j * 1024 + it * 256 + tid] == e) ? 1 : 0;
#pragma unroll
    for (int off = 16; off; off >>= 1) c += __shfl_xor_sync(0xffffffffu, c, off);
    if (lane == 0) wsum[w] = c;
    __syncthreads();
    if (tid == 0) {
        int tot = 0;
#pragma unroll
        for (int i = 0; i < 8; i++) tot += wsum[i];
        g_blk[e][j] = tot;
    }
}

__global__ void __launch_bounds__(256) scatter_kernel()
{
    const int e = blockIdx.x, j = blockIdx.y;
    const int tid = threadIdx.x, lane = tid & 31, w = tid >> 5;
    __shared__ int warp_tot[8];
    __shared__ int s_base;

    if (tid == 0) {
        int base = 0, tot = 0;
#pragma unroll
        for (int i = 0; i < 16; i++) {
            const int v = g_blk[e][i];
            if (i < j) base += v;
            tot += v;
        }
        s_base = base;
        if (j == 0) g_counts[e] = tot;
    }
    __syncthreads();

#pragma unroll 1
    for (int it = 0; it < 4; it++) {
        const int slot = j * 1024 + it * 256 + tid;
        const int flag = (g_top_idx[slot] == e) ? 1 : 0;
        const unsigned bal = __ballot_sync(0xffffffffu, flag);
        const int pre = __popc(bal & ((1u << lane) - 1u));
        if (lane == 0) warp_tot[w] = __popc(bal);
        __syncthreads();
        int woff = 0;
        for (int i = 0; i < w; i++) woff += warp_tot[i];
        if (flag) g_rows[e * T_TOK + s_base + woff + pre] = slot;
        __syncthreads();
        if (tid == 0) {
            int tt = 0;
#pragma unroll
            for (int i = 0; i < 8; i++) tt += warp_tot[i];
            s_base += tt;
        }
        __syncthreads();
    }
}

// ============================================================================
// HMMA GEMMs, 1-term fp16. CTA 128x128, 8 warps (2Mx4N), K chunk 32.
// cp.async 4-stage pipeline; rows padded to 80B. Stage: [A 10240][B 10240].
// ============================================================================
#define ROWB   80
#define MATB   (128 * ROWB)        // 10240
#define STAGE  (2 * MATB)          // 20480
#define NSTG   4
#define SMEM_DYN (NSTG * STAGE)    // 81920

// ---- up GEMM + SiLU: A = x(fp16), B = w13 interleaved gate/up. grid (E*64, 8)
__global__ void __launch_bounds__(256, 2) up_gemm_mma()
{
    const int e  = blockIdx.x >> 6;
    const int mt = blockIdx.x & 63;
    const int cnt = g_counts[e];
    const int m0 = mt * 128;
    if (m0 >= cnt) return;
    const int rcount = min(128, cnt - m0);
    const int ib = blockIdx.y * 64;

    extern __shared__ char sm[];
    const u32 smu = smem_u32(sm);
    __shared__ int s_slot[128];
    __shared__ int s_tok[128];

    const int tid = threadIdx.x, lane = tid & 31, wid = tid >> 5;
    const int wm = wid >> 2, wn = wid & 3;

    if (tid < 128) {
        const int sl = g_rows[e * T_TOK + m0 + min(tid, rcount - 1)];
        s_slot[tid] = sl;
        s_tok[tid] = sl >> 1;
    }
    __syncthreads();

    // 4 cp.async descriptors/thread: 2 matrices x 512 16B-chunks / 256 threads
    const char* srcs[4];
    u32 dsts[4];
#pragma unroll
    for (int t = 0; t < 4; t++) {
        const int idx = tid + t * 256;
        const int mat = idx >> 9, rr = (idx >> 2) & 127, ch = idx & 3;
        dsts[t] = (u32)(mat * MATB + rr * ROWB + ch * 16);
        if (mat == 0) srcs[t] = (const char*)(g_xh + (size_t)s_tok[rr] * H_DIM + ch * 8);
        else {
            const int wrow = (rr & 1) ? (512 + ib + (rr >> 1)) : (ib + (rr >> 1));
            srcs[t] = (const char*)(g_w13h + ((size_t)e * 1024 + wrow) * H_DIM + ch * 8);
        }
    }

    float acc[4][4][4];
#pragma unroll
    for (int i = 0; i < 4; i++)
#pragma unroll
        for (int j = 0; j < 4; j++)
#pragma unroll
            for (int q = 0; q < 4; q++) acc[i][j][q] = 0.f;

    // prologue: 3 stages
#pragma unroll
    for (int s = 0; s < 3; s++) {
#pragma unroll
        for (int t = 0; t < 4; t++) CPA16(smu + s * STAGE + dsts[t], srcs[t] + (size_t)s * 64);
        CPCOMMIT();
    }

    const u32 lrow = (u32)(lane & 15) * ROWB + (u32)((lane >> 4) << 4);

#pragma unroll 1
    for (int c = 0; c < 32; c++) {
        const int p = c & 3;
        CPWAIT2();
        __syncthreads();
        if (c + 3 < 32) {
            const u32 sb = smu + ((c + 3) & 3) * STAGE;
            const size_t go = (size_t)(c + 3) * 64;
#pragma unroll
            for (int t = 0; t < 4; t++) CPA16(sb + dsts[t], srcs[t] + go);
        }
        CPCOMMIT();

        const u32 aB = smu + p * STAGE + (u32)(wm * 64) * ROWB + lrow;
        const u32 bB = smu + p * STAGE + MATB + (u32)(wn * 32) * ROWB + lrow;
#pragma unroll
        for (int kk = 0; kk < 2; kk++) {
            const u32 ko = kk * 32;
            u32 a[4][4], b[2][4];
#pragma unroll
            for (int mi = 0; mi < 4; mi++)
                ldsm4(a[mi][0], a[mi][1], a[mi][2], a[mi][3], aB + mi * 16 * ROWB + ko);
            ldsm4(b[0][0], b[0][1], b[0][2], b[0][3], bB + ko);
            ldsm4(b[1][0], b[1][1], b[1][2], b[1][3], bB + 16 * ROWB + ko);
#pragma unroll
            for (int mi = 0; mi < 4; mi++)
#pragma unroll
                for (int nj = 0; nj < 4; nj++) {
                    const int g = nj >> 1, o = nj & 1;
                    mma_f16(acc[mi][nj], a[mi], b[g][o], b[g][o + 2]);
                }
        }
    }

    // epilogue: (c0,c1)/(c2,c3) = (gate, up) for rows m, m+8
    const int qr = lane >> 2, qc = lane & 3;
#pragma unroll
    for (int mi = 0; mi < 4; mi++) {
        const int mlo = wm * 64 + mi * 16 + qr;
#pragma unroll
        for (int nj = 0; nj < 4; nj++) {
            const int icol = ib + wn * 16 + nj * 4 + qc;
            const float* a4 = acc[mi][nj];
            if (mlo < rcount) {
                const float g = a4[0], u = a4[1];
                g_acth[(size_t)s_slot[mlo] * I_DIM + icol] =
                    __float2half_rn(g / (1.f + __expf(-g)) * u);
            }
            if (mlo + 8 < rcount) {
                const float g = a4[2], u = a4[3];
                g_acth[(size_t)s_slot[mlo + 8] * I_DIM + icol] =
                    __float2half_rn(g / (1.f + __expf(-g)) * u);
            }
        }
    }
}

// ---- down GEMM: A = act(fp16), B = w2. K=512 (16 chunks). grid (E*64, 8) ----
__global__ void __launch_bounds__(256, 2) down_gemm_mma()
{
    const int e  = blockIdx.x >> 6;
    const int mt = blockIdx.x & 63;
    const int cnt = g_counts[e];
    const int m0 = mt * 128;
    if (m0 >= cnt) return;
    const int rcount = min(128, cnt - m0);
    const int hb = blockIdx.y * 128;

    extern __shared__ char sm[];
    const u32 smu = smem_u32(sm);
    __shared__ int   s_slot[128];
    __shared__ float s_wt[128];

    const int tid = threadIdx.x, lane = tid & 31, wid = tid >> 5;
    const int wm = wid >> 2, wn = wid & 3;

    if (tid < 128) {
        const int sl = g_rows[e * T_TOK + m0 + min(tid, rcount - 1)];
        s_slot[tid] = sl;
        s_wt[tid] = g_top_w[sl] * SCALE_F;
    }
    __syncthreads();

    const char* srcs[4];
    u32 dsts[4];
#pragma unroll
    for (int t = 0; t < 4; t++) {
        const int idx = tid + t * 256;
        const int mat = idx >> 9, rr = (idx >> 2) & 127, ch = idx & 3;
        dsts[t] = (u32)(mat * MATB + rr * ROWB + ch * 16);
        if (mat == 0) srcs[t] = (const char*)(g_acth + (size_t)s_slot[rr] * I_DIM + ch * 8);
        else srcs[t] = (const char*)(g_w2h + ((size_t)e * H_DIM + hb + rr) * I_DIM + ch * 8);
    }

    float acc[4][4][4];
#pragma unroll
    for (int i = 0; i < 4; i++)
#pragma unroll
        for (int j = 0; j < 4; j++)
#pragma unroll
            for (int q = 0; q < 4; q++) acc[i][j][q] = 0.f;

#pragma unroll
    for (int s = 0; s < 3; s++) {
#pragma unroll
        for (int t = 0; t < 4; t++) CPA16(smu + s * STAGE + dsts[t], srcs[t] + (size_t)s * 64);
        CPCOMMIT();
    }

    const u32 lrow = (u32)(lane & 15) * ROWB + (u32)((lane >> 4) << 4);

#pragma unroll 1
    for (int c = 0; c < 16; c++) {
        const int p = c & 3;
        CPWAIT2();
        __syncthreads();
        if (c + 3 < 16) {
            const u32 sb = smu + ((c + 3) & 3) * STAGE;
            const size_t go = (size_t)(c + 3) * 64;
#pragma unroll
            for (int t = 0; t < 4; t++) CPA16(sb + dsts[t], srcs[t] + go);
        }
        CPCOMMIT();

        const u32 aB = smu + p * STAGE + (u32)(wm * 64) * ROWB + lrow;
        const u32 bB = smu + p * STAGE + MATB + (u32)(wn * 32) * ROWB + lrow;
#pragma unroll
        for (int kk = 0; kk < 2; kk++) {
            const u32 ko = kk * 32;
            u32 a[4][4], b[2][4];
#pragma unroll
            for (int mi = 0; mi < 4; mi++)
                ldsm4(a[mi][0], a[mi][1], a[mi][2], a[mi][3], aB + mi * 16 * ROWB + ko);
            ldsm4(b[0][0], b[0][1], b[0][2], b[0][3], bB + ko);
            ldsm4(b[1][0], b[1][1], b[1][2], b[1][3], bB + 16 * ROWB + ko);
#pragma unroll
            for (int mi = 0; mi < 4; mi++)
#pragma unroll
                for (int nj = 0; nj < 4; nj++) {
                    const int g = nj >> 1, o = nj & 1;
                    mma_f16(acc[mi][nj], a[mi], b[g][o], b[g][o + 2]);
                }
        }
    }

    const int qr = lane >> 2, qc = lane & 3;
#pragma unroll
    for (int mi = 0; mi < 4; mi++) {
        const int mlo = wm * 64 + mi * 16 + qr;
#pragma unroll
        for (int nj = 0; nj < 4; nj++) {
            const int n0 = hb + wn * 32 + nj * 8 + 2 * qc;
            const float* a4 = acc[mi][nj];
            if (mlo < rcount) {
                const float wt = s_wt[mlo];
                float2 v; v.x = wt * a4[0]; v.y = wt * a4[1];
                *(float2*)(g_y + (size_t)s_slot[mlo] * H_DIM + n0) = v;
            }
            if (mlo + 8 < rcount) {
                const float wt = s_wt[mlo + 8];
                float2 v; v.x = wt * a4[2]; v.y = wt * a4[3];
                *(float2*)(g_y + (size_t)s_slot[mlo + 8] * H_DIM + n0) = v;
            }
        }
    }
}

// ============================================================================
// finalize (proven)
// ============================================================================
__global__ void __launch_bounds__(256) finalize_kernel(
    const float* __restrict__ x, float* __restrict__ out)
{
    const int t = blockIdx.x;
    const float zs = g_zero_scale[t];
    const bool r0 = g_top_idx[2 * t]     < E_EXP;
    const bool r1 = g_top_idx[2 * t + 1] < E_EXP;
    const int h = threadIdx.x * 4;

    float4 xv = *(const float4*)(x + (size_t)t * H_DIM + h);
    float4 o;
    o.x = zs * xv.x; o.y = zs * xv.y; o.z = zs * xv.z; o.w = zs * xv.w;
    if (r0) {
        float4 y = *(const float4*)(g_y + (size_t)(2 * t) * H_DIM + h);
        o.x += y.x; o.y += y.y; o.z += y.z; o.w += y.w;
    }
    if (r1) {
        float4 y = *(const float4*)(g_y + (size_t)(2 * t + 1) * H_DIM + h);
        o.x += y.x; o.y += y.y; o.z += y.z; o.w += y.w;
    }
    *(float4*)(out + (size_t)t * H_DIM + h) = o;
}

// ============================================================================
// launch
// ============================================================================
extern "C" void kernel_launch(void* const* d_in, const int* in_sizes, int n_in,
                              void* d_out, int out_size)
{
    const float* x    = (const float*)d_in[0];
    const float* rw   = (const float*)d_in[1];
    const float* bias = (const float*)d_in[2];
    const float* w13  = (const float*)d_in[3];
    const float* w2   = (const float*)d_in[4];
    float* out = (float*)d_out;

    cudaFuncSetAttribute(up_gemm_mma,   cudaFuncAttributeMaxDynamicSharedMemorySize, SMEM_DYN);
    cudaFuncSetAttribute(down_gemm_mma, cudaFuncAttributeMaxDynamicSharedMemorySize, SMEM_DYN);

    cvt_w_kernel<<<(int)((W13_ELEMS + (size_t)E_EXP * H_DIM * I_DIM) / 1024), 256>>>(w13, w2);
    router_kernel<<<T_TOK / 8, 256>>>(x, rw, bias);

    dim3 gl(E_EXP, 16);
    count_kernel<<<gl, 256>>>();
    scatter_kernel<<<gl, 256>>>();

    dim3 gu(E_EXP * 64, 8);
    up_gemm_mma<<<gu, 256, SMEM_DYN>>>();

    dim3 gd(E_EXP * 64, 8);
    down_gemm_mma<<<gd, 256, SMEM_DYN>>>();

    finalize_kernel<<<T_TOK, 256>>>(x, out);
}